// round 1
// baseline (speedup 1.0000x reference)
#include <cuda_runtime.h>

// ---------------- problem constants ----------------
#define Bn      8
#define Nn      40962
#define Dn      40
#define Hn      512
#define DDn     32
#define KTOT    160          // 4 neighbors * 40 dims
#define M_TOT   (Bn*Nn)      // 327696 rows

// ---------------- tiling ----------------
#define TM        64         // rows per block
#define NTHREADS  256
#define KT        8          // W1 k-tile depth
#define HHALF     256        // process H=512 in two halves
#define ZST       68         // padded Z row stride (floats), 16B aligned, spreads banks
#define HST       260        // padded H row stride (floats), conflict-free column reads
#define NBLK      ((M_TOT + TM - 1)/TM)   // 5121

// ---------------- smem layout (bytes) ----------------
#define OFF_ZS    0
#define SZ_ZS     (KTOT*ZST*4)            // 43520
#define OFF_W1S   (OFF_ZS + SZ_ZS)
#define SZ_W1S    (KT*HHALF*4)            // 8192
#define OFF_HS    (OFF_W1S + SZ_W1S)
#define SZ_HS     (TM*HST*4)              // 66560
#define OFF_W2S   (OFF_HS + SZ_HS)
#define SZ_W2S    (Hn*DDn*4)              // 65536
#define OFF_B1S   (OFF_W2S + SZ_W2S)
#define SZ_B1S    (Hn*4)                  // 2048
#define OFF_B2S   (OFF_B1S + SZ_B1S)
#define SZ_B2S    (128)
#define OFF_BASE  (OFF_B2S + SZ_B2S)
#define SZ_BASE   (TM*4*4)                // 1024
#define SMEM_BYTES (OFF_BASE + SZ_BASE)   // 187008

typedef unsigned long long u64;

// packed f32x2 FMA: 2 FMAs per instruction (FFMA2) — 2x FFMA throughput on sm_103a
__device__ __forceinline__ void ffma2(u64 &acc, u64 a, u64 b) {
    asm("fma.rn.f32x2 %0, %1, %2, %0;" : "+l"(acc) : "l"(a), "l"(b));
}
__device__ __forceinline__ u64 splat2(float x) {
    u64 r; asm("mov.b64 %0, {%1, %1};" : "=l"(r) : "f"(x)); return r;
}
__device__ __forceinline__ float2 unpk(u64 v) {
    float2 f; asm("mov.b64 {%0, %1}, %2;" : "=f"(f.x), "=f"(f.y) : "l"(v)); return f;
}
// jax.nn.gelu default (approximate=True): 0.5*x*(1+tanh(0.7978845608*(x+0.044715 x^3)))
__device__ __forceinline__ float gelu_t(float x) {
    float u = x * (0.7978845608028654f + 0.0356774081f * x * x);
    float t; asm("tanh.approx.f32 %0, %1;" : "=f"(t) : "f"(u));
    return 0.5f * x * (1.0f + t);
}

// scratch x buffer for ping-pong between steps (double-buffered Euler update)
__device__ float g_xbuf[(size_t)M_TOT * Dn];

__global__ void __launch_bounds__(NTHREADS, 1)
step_kernel(const float* __restrict__ src, float* __restrict__ dst,
            const int*   __restrict__ index,
            const float* __restrict__ W1, const float* __restrict__ b1,
            const float* __restrict__ W2, const float* __restrict__ b2)
{
    extern __shared__ char smem[];
    float* Zs  = (float*)(smem + OFF_ZS);    // [160][ZST]  transposed gathered z
    float* W1s = (float*)(smem + OFF_W1S);   // [KT][HHALF]
    float* Hs  = (float*)(smem + OFF_HS);    // [TM][HST]
    float* W2s = (float*)(smem + OFF_W2S);   // [512][32]
    float* b1s = (float*)(smem + OFF_B1S);
    float* b2s = (float*)(smem + OFF_B2S);
    int*   bas = (int*)  (smem + OFF_BASE);  // [TM*4] gather row bases (element offsets)

    const int tid  = threadIdx.x;
    const int lane = tid & 31;
    const int rg   = tid >> 5;               // warp id = row group (8 rows each)
    const int m0   = blockIdx.x * TM;
    const int rows_valid = min(TM, M_TOT - m0);

    // ---- gather index precompute ----
    if (tid < TM*4) {
        int r = tid >> 2, k = tid & 3;
        int base = 0;
        if (r < rows_valid) {
            int m = m0 + r;
            int b = m / Nn;
            int n = m - b * Nn;
            int idx = __ldg(&index[n*4 + k]);
            base = (b * Nn + idx) * Dn;
        }
        bas[tid] = base;
    }
    // ---- stage W2, b1, b2 ----
    #pragma unroll
    for (int i = tid; i < (Hn*DDn)/4; i += NTHREADS)
        ((float4*)W2s)[i] = __ldg(&((const float4*)W2)[i]);
    if (tid < Hn/4) ((float4*)b1s)[tid] = __ldg(&((const float4*)b1)[tid]);
    if (tid < DDn/4) ((float4*)b2s)[tid] = __ldg(&((const float4*)b2)[tid]);
    __syncthreads();

    // ---- gather Z tile: 64 rows x 4 nbrs x 40 floats, stored transposed ----
    #pragma unroll
    for (int it = 0; it < 10; ++it) {
        int t  = it * NTHREADS + tid;        // < 2560 float4 units
        int d4 = t % 10;
        int rk = t / 10;
        int r  = rk >> 2;
        int k  = rk & 3;
        float4 v = __ldg((const float4*)(src + bas[rk] + d4*4));
        int kd = k * Dn + d4 * 4;
        Zs[(kd+0)*ZST + r] = v.x;
        Zs[(kd+1)*ZST + r] = v.y;
        Zs[(kd+2)*ZST + r] = v.z;
        Zs[(kd+3)*ZST + r] = v.w;
    }

    // W1 tile load mapping (2 float4 per thread per k-chunk)
    const int i4a = tid,        kkA = i4a >> 6, c4A = i4a & 63;
    const int i4b = tid + 256,  kkB = i4b >> 6, c4B = i4b & 63;

    u64 oacc[4] = {0ULL, 0ULL, 0ULL, 0ULL};  // phase-2 accumulators (8 out cols), carried over halves

    #pragma unroll 1
    for (int hh = 0; hh < 2; ++hh) {
        // ------------- phase 1: h_pre[64][256] = Z[64][160] x W1half[160][256] -------------
        u64 acc[8][4];
        #pragma unroll
        for (int r = 0; r < 8; ++r)
            #pragma unroll
            for (int j = 0; j < 4; ++j) acc[r][j] = 0ULL;

        const float* W1g = W1 + hh * HHALF;

        // prefetch first W1 tile
        float4 pfA = __ldg((const float4*)(W1g + kkA*Hn) + c4A);
        float4 pfB = __ldg((const float4*)(W1g + kkB*Hn) + c4B);

        #pragma unroll 1
        for (int k0 = 0; k0 < KTOT; k0 += KT) {
            __syncthreads();                 // prior consumers of W1s done
            ((float4*)W1s)[i4a] = pfA;
            ((float4*)W1s)[i4b] = pfB;
            __syncthreads();                 // tile visible
            if (k0 + KT < KTOT) {            // prefetch next tile (hides L2 latency)
                pfA = __ldg((const float4*)(W1g + (k0+KT+kkA)*Hn) + c4A);
                pfB = __ldg((const float4*)(W1g + (k0+KT+kkB)*Hn) + c4B);
            }
            #pragma unroll
            for (int kk = 0; kk < KT; ++kk) {
                const float* zrow = &Zs[(k0+kk)*ZST + rg*8];
                float4 z0 = *(const float4*)(zrow);
                float4 z1 = *(const float4*)(zrow + 4);
                ulonglong2 w0 = *(const ulonglong2*)&W1s[kk*HHALF + lane*4];
                ulonglong2 w1 = *(const ulonglong2*)&W1s[kk*HHALF + lane*4 + 128];
                u64 zp[8];
                zp[0]=splat2(z0.x); zp[1]=splat2(z0.y); zp[2]=splat2(z0.z); zp[3]=splat2(z0.w);
                zp[4]=splat2(z1.x); zp[5]=splat2(z1.y); zp[6]=splat2(z1.z); zp[7]=splat2(z1.w);
                #pragma unroll
                for (int r = 0; r < 8; ++r) {
                    ffma2(acc[r][0], zp[r], w0.x);
                    ffma2(acc[r][1], zp[r], w0.y);
                    ffma2(acc[r][2], zp[r], w1.x);
                    ffma2(acc[r][3], zp[r], w1.y);
                }
            }
        }

        // ------------- bias + gelu -> Hs -------------
        #pragma unroll
        for (int r = 0; r < 8; ++r) {
            int row = rg*8 + r;
            #pragma unroll
            for (int j = 0; j < 2; ++j) {
                int c = lane*4 + j*128;
                float2 p0 = unpk(acc[r][2*j+0]);
                float2 p1 = unpk(acc[r][2*j+1]);
                float4 h;
                h.x = gelu_t(p0.x + b1s[hh*HHALF + c + 0]);
                h.y = gelu_t(p0.y + b1s[hh*HHALF + c + 1]);
                h.z = gelu_t(p1.x + b1s[hh*HHALF + c + 2]);
                h.w = gelu_t(p1.y + b1s[hh*HHALF + c + 3]);
                *(float4*)&Hs[row*HST + c] = h;
            }
        }
        __syncthreads();

        // ------------- phase 2: out[64][32] += Hs[64][256] x W2half[256][32] -------------
        {
            int row_sub = lane >> 2;
            int ocq     = lane & 3;
            int row     = rg*8 + row_sub;
            const float* hrow = &Hs[row*HST];
            const float* w2p  = &W2s[hh*HHALF*DDn + ocq*8];
            #pragma unroll 4
            for (int k = 0; k < HHALF; k += 4) {
                float4 h4 = *(const float4*)&hrow[k];
                #pragma unroll
                for (int q = 0; q < 4; ++q) {
                    u64 hs = splat2(((const float*)&h4)[q]);
                    const float* wr = w2p + (k+q)*DDn;
                    ulonglong2 wA = *(const ulonglong2*)(wr);
                    ulonglong2 wB = *(const ulonglong2*)(wr + 4);
                    ffma2(oacc[0], hs, wA.x);
                    ffma2(oacc[1], hs, wA.y);
                    ffma2(oacc[2], hs, wB.x);
                    ffma2(oacc[3], hs, wB.y);
                }
            }
        }
        // next half's first k0 __syncthreads() protects Hs/W1s reuse
    }

    // ------------- epilogue: dst = self_row + 0.1*(out + b2); dims 32..39 copied -------------
    {
        int row_sub = lane >> 2;
        int ocq     = lane & 3;
        int row     = rg*8 + row_sub;
        if (row < rows_valid) {
            int m = m0 + row;
            float o[8];
            #pragma unroll
            for (int p = 0; p < 4; ++p) {
                float2 v = unpk(oacc[p]);
                o[2*p] = v.x; o[2*p+1] = v.y;
            }
            float4 w0, w1;
            #pragma unroll
            for (int j = 0; j < 4; ++j) {
                int oc = ocq*8 + j;
                ((float*)&w0)[j] = Zs[oc*ZST + row] + 0.1f * (o[j] + b2s[oc]);
            }
            #pragma unroll
            for (int j = 0; j < 4; ++j) {
                int oc = ocq*8 + 4 + j;
                ((float*)&w1)[j] = Zs[oc*ZST + row] + 0.1f * (o[4+j] + b2s[oc]);
            }
            float* drow = dst + (size_t)m * Dn;
            *(float4*)(drow + ocq*8)     = w0;
            *(float4*)(drow + ocq*8 + 4) = w1;
            if (ocq == 3) {  // static dims 32..39 (self row, from Z tile k=0)
                float4 s0, s1;
                #pragma unroll
                for (int j = 0; j < 4; ++j) ((float*)&s0)[j] = Zs[(32+j)*ZST + row];
                #pragma unroll
                for (int j = 0; j < 4; ++j) ((float*)&s1)[j] = Zs[(36+j)*ZST + row];
                *(float4*)(drow + 32) = s0;
                *(float4*)(drow + 36) = s1;
            }
        }
    }
}

extern "C" void kernel_launch(void* const* d_in, const int* in_sizes, int n_in,
                              void* d_out, int out_size)
{
    const float* x     = (const float*)d_in[0];
    const int*   index = (const int*)  d_in[1];
    const float* W1    = (const float*)d_in[2];
    const float* b1    = (const float*)d_in[3];
    const float* W2    = (const float*)d_in[4];
    const float* b2    = (const float*)d_in[5];
    float* out = (float*)d_out;

    float* buf = nullptr;
    cudaGetSymbolAddress((void**)&buf, g_xbuf);

    cudaFuncSetAttribute(step_kernel, cudaFuncAttributeMaxDynamicSharedMemorySize, SMEM_BYTES);

    dim3 grid(NBLK), block(NTHREADS);
    // 4 Euler steps, ping-pong buffers: in -> buf -> out -> buf -> out
    step_kernel<<<grid, block, SMEM_BYTES>>>(x,   buf, index, W1, b1, W2, b2);
    step_kernel<<<grid, block, SMEM_BYTES>>>(buf, out, index, W1, b1, W2, b2);
    step_kernel<<<grid, block, SMEM_BYTES>>>(out, buf, index, W1, b1, W2, b2);
    step_kernel<<<grid, block, SMEM_BYTES>>>(buf, out, index, W1, b1, W2, b2);
}

// round 3
// speedup vs baseline: 3.2791x; 3.2791x over previous
#include <cuda_runtime.h>
#include <cstdint>

typedef unsigned int u32;

// ---------------- problem constants ----------------
#define Bn 8
#define Nn 40962
#define Dn 40
#define Hn 512
#define DDn 32
#define KTOT 160               // 4 neighbors * 40
#define M_TOT (Bn*Nn)          // 327696
#define TMm 128                // rows per CTA
#define NTH 256
#define NBLK ((M_TOT + TMm - 1)/TMm)   // 2561
#define KA1 20                 // GEMM1 k-atoms (160/8)

// smem (floats): Zfrag 20480 | W2frag 16384 | b1 512 | b2 32 | bas 512
#define SM_Z    0
#define SM_W2   20480
#define SM_B1   (SM_W2 + 16384)
#define SM_B2   (SM_B1 + 512)
#define SM_BAS  (SM_B2 + 32)
#define SM_FLOATS (SM_BAS + 512)
#define SMEM_BYTES (SM_FLOATS*4)       // 151680

// ---------------- helpers ----------------
__device__ __forceinline__ u32 tf32b(float x) {
    u32 r; asm("cvt.rna.tf32.f32 %0, %1;" : "=r"(r) : "f"(x));
    return r;
}
__device__ __forceinline__ float gelu_t(float x) {
    float u = x * (0.7978845608028654f + 0.0356774081f * x * x);
    float t; asm("tanh.approx.f32 %0, %1;" : "=f"(t) : "f"(u));
    return 0.5f * x * (1.0f + t);
}

// m16n8k8 tf32 HMMA: D(f32) += A(tf32) * B(tf32)
#define MMA4(D, A, b0, b1) \
    asm("mma.sync.aligned.m16n8k8.row.col.f32.tf32.tf32.f32 " \
        "{%0,%1,%2,%3}, {%4,%5,%6,%7}, {%8,%9}, {%0,%1,%2,%3};" \
        : "+f"((D)[0]), "+f"((D)[1]), "+f"((D)[2]), "+f"((D)[3]) \
        : "r"((A)[0]), "r"((A)[1]), "r"((A)[2]), "r"((A)[3]), "r"(b0), "r"(b1))

// ---------------- global scratch ----------------
// W1 B-fragments: [ka(20)][nblk(8)][pair(4)][lane(32)][q(4)]
__device__ float g_W1f[KA1 * 8 * 4 * 32 * 4];        // 163840 floats
// W2 B-fragments (k-permuted to match GEMM1 D layout): [gka(64)][pair(2)][lane(32)][q(4)]
__device__ float g_W2f[64 * 2 * 32 * 4];             // 16384 floats
__device__ float g_xbuf[(size_t)M_TOT * Dn];         // ping-pong state

// prep: W1 -> B-fragment order, tf32-rounded.
// value(ka,nblk,pair,lane,q): k = ka*8 + lane%4 + (q%2)*4
//                             n = nblk*64 + pair*16 + (q/2)*8 + lane/4
__global__ void prep_w1f(const float* __restrict__ W1) {
    int i = blockIdx.x * 256 + threadIdx.x;
    if (i >= KA1 * 8 * 4 * 32 * 4) return;
    int q    = i & 3;
    int lane = (i >> 2) & 31;
    int pair = (i >> 7) & 3;
    int nblk = (i >> 9) & 7;
    int ka   = i >> 12;
    int k = ka * 8 + (lane & 3) + (q & 1) * 4;
    int n = nblk * 64 + pair * 16 + (q >> 1) * 8 + (lane >> 2);
    g_W1f[i] = __uint_as_float(tf32b(__ldg(&W1[k * Hn + n])));
}

// prep: W2 -> B-fragment order with k-permutation pi(k) = (k<4) ? 2k : 2(k-4)+1.
// value(gka,pair,lane,q): w2row = gka*8 + 2*(lane%4) + (q%2)
//                         n     = pair*16 + (q/2)*8 + lane/4
__global__ void prep_w2f(const float* __restrict__ W2) {
    int i = blockIdx.x * 256 + threadIdx.x;
    if (i >= 64 * 2 * 32 * 4) return;
    int q    = i & 3;
    int lane = (i >> 2) & 31;
    int pair = (i >> 7) & 1;
    int gka  = i >> 8;
    int r = gka * 8 + 2 * (lane & 3) + (q & 1);
    int n = pair * 16 + (q >> 1) * 8 + (lane >> 2);
    g_W2f[i] = __uint_as_float(tf32b(__ldg(&W2[r * DDn + n])));
}

// ---------------- fused Euler step ----------------
__global__ void __launch_bounds__(NTH, 1)
step_kernel(const float* __restrict__ src, float* __restrict__ dst,
            const int* __restrict__ index,
            const float* __restrict__ W1f, const float* __restrict__ W2f,
            const float* __restrict__ b1, const float* __restrict__ b2)
{
    extern __shared__ float sm[];
    float* Zf  = sm + SM_Z;      // A-frags of Z: [mb(8)][ka(20)][lane(32)][slot(4)]
    float* W2s = sm + SM_W2;
    float* b1s = sm + SM_B1;
    float* b2s = sm + SM_B2;
    int*   bas = (int*)(sm + SM_BAS);
    float* red = sm + SM_Z;      // reduction reuses Zf after GEMMs

    const int tid  = threadIdx.x;
    const int lane = tid & 31;
    const int wid  = tid >> 5;
    const int wm   = wid & 3;    // M warp: rows wm*32
    const int wn   = wid >> 2;   // N warp: 64-col slice within 128-chunk
    const int m0   = blockIdx.x * TMm;
    const int rows_valid = min(TMm, M_TOT - m0);

    // gather bases
    for (int i = tid; i < TMm * 4; i += NTH) {
        int r = i >> 2, k = i & 3;
        int base = 0;
        if (r < rows_valid) {
            int m = m0 + r, b = m / Nn, n = m - b * Nn;
            base = (b * Nn + __ldg(&index[n * 4 + k])) * Dn;
        }
        bas[i] = base;
    }
    // stage W2 frags + biases
    #pragma unroll
    for (int i = 0; i < 16; ++i)
        ((float4*)W2s)[tid + i * NTH] = __ldg(((const float4*)W2f) + tid + i * NTH);
    if (tid < 128) ((float4*)b1s)[tid] = __ldg(((const float4*)b1) + tid);
    if (tid < 8)   ((float4*)b2s)[tid] = __ldg(((const float4*)b2) + tid);
    __syncthreads();

    // ---- gather Z -> A-fragment layout, tf32-rounded ----
    // element (row r, K): mb=r/16, rr=r%16, ka=K/8, c=K%8
    //   lane' = (rr%8)*4 + c%4 ; slot = rr/8 + 2*(c/4)
    #pragma unroll 1
    for (int it = 0; it < 20; ++it) {
        int t  = it * NTH + tid;            // 5120 float4
        int d4 = t % 10, rk = t / 10;
        int r  = rk >> 2, kn = rk & 3;
        float4 v = __ldg((const float4*)(src + bas[rk] + d4 * 4));
        int K  = kn * 40 + d4 * 4;
        int ka = K >> 3, c0 = K & 7;
        int mb = r >> 4, rr = r & 15;
        int slot = (rr >> 3) + ((c0 >> 2) << 1);
        int idx0 = (((mb * KA1 + ka) * 32) + (rr & 7) * 4) * 4 + slot;
        Zf[idx0]      = __uint_as_float(tf32b(v.x));
        Zf[idx0 + 4]  = __uint_as_float(tf32b(v.y));
        Zf[idx0 + 8]  = __uint_as_float(tf32b(v.z));
        Zf[idx0 + 12] = __uint_as_float(tf32b(v.w));
    }
    __syncthreads();

    float d2[2][4][4];
    #pragma unroll
    for (int m = 0; m < 2; ++m)
        #pragma unroll
        for (int a = 0; a < 4; ++a)
            #pragma unroll
            for (int q = 0; q < 4; ++q) d2[m][a][q] = 0.f;

    const float4* Bg = (const float4*)W1f;

    // ---- 4 H-chunks of 128 cols; each warp owns a 32-row x 64-col tile ----
    #pragma unroll 1
    for (int nc = 0; nc < 4; ++nc) {
        const int nblk = nc * 2 + wn;
        float d1[2][8][4];
        #pragma unroll
        for (int m = 0; m < 2; ++m)
            #pragma unroll
            for (int a = 0; a < 8; ++a)
                #pragma unroll
                for (int q = 0; q < 4; ++q) d1[m][a][q] = 0.f;

        // distance-2 register prefetch of W1 B-frags (L2-resident)
        float4 pfA[4], pfB[4];
        #pragma unroll
        for (int p = 0; p < 4; ++p) {
            pfA[p] = __ldg(Bg + ((0 * 8 + nblk) * 4 + p) * 32 + lane);
            pfB[p] = __ldg(Bg + ((1 * 8 + nblk) * 4 + p) * 32 + lane);
        }

        #pragma unroll 1
        for (int ka = 0; ka < KA1; ka += 2) {
            // ---- even k-atom (pfA) ----
            {
                u32 a0[4], a1[4];
                float4 av0 = *(const float4*)&Zf[(((wm*2+0) * KA1 + ka) * 32 + lane) * 4];
                float4 av1 = *(const float4*)&Zf[(((wm*2+1) * KA1 + ka) * 32 + lane) * 4];
                a0[0]=__float_as_uint(av0.x); a0[1]=__float_as_uint(av0.y);
                a0[2]=__float_as_uint(av0.z); a0[3]=__float_as_uint(av0.w);
                a1[0]=__float_as_uint(av1.x); a1[1]=__float_as_uint(av1.y);
                a1[2]=__float_as_uint(av1.z); a1[3]=__float_as_uint(av1.w);
                #pragma unroll
                for (int p = 0; p < 4; ++p) {
                    u32 bx=__float_as_uint(pfA[p].x), by=__float_as_uint(pfA[p].y);
                    u32 bz=__float_as_uint(pfA[p].z), bw=__float_as_uint(pfA[p].w);
                    MMA4(d1[0][2*p],   a0, bx, by);
                    MMA4(d1[1][2*p],   a1, bx, by);
                    MMA4(d1[0][2*p+1], a0, bz, bw);
                    MMA4(d1[1][2*p+1], a1, bz, bw);
                }
                if (ka + 2 < KA1) {
                    #pragma unroll
                    for (int p = 0; p < 4; ++p)
                        pfA[p] = __ldg(Bg + (((ka+2) * 8 + nblk) * 4 + p) * 32 + lane);
                }
            }
            // ---- odd k-atom (pfB) ----
            {
                u32 a0[4], a1[4];
                float4 av0 = *(const float4*)&Zf[(((wm*2+0) * KA1 + ka+1) * 32 + lane) * 4];
                float4 av1 = *(const float4*)&Zf[(((wm*2+1) * KA1 + ka+1) * 32 + lane) * 4];
                a0[0]=__float_as_uint(av0.x); a0[1]=__float_as_uint(av0.y);
                a0[2]=__float_as_uint(av0.z); a0[3]=__float_as_uint(av0.w);
                a1[0]=__float_as_uint(av1.x); a1[1]=__float_as_uint(av1.y);
                a1[2]=__float_as_uint(av1.z); a1[3]=__float_as_uint(av1.w);
                #pragma unroll
                for (int p = 0; p < 4; ++p) {
                    u32 bx=__float_as_uint(pfB[p].x), by=__float_as_uint(pfB[p].y);
                    u32 bz=__float_as_uint(pfB[p].z), bw=__float_as_uint(pfB[p].w);
                    MMA4(d1[0][2*p],   a0, bx, by);
                    MMA4(d1[1][2*p],   a1, bx, by);
                    MMA4(d1[0][2*p+1], a0, bz, bw);
                    MMA4(d1[1][2*p+1], a1, bz, bw);
                }
                if (ka + 3 < KA1) {
                    #pragma unroll
                    for (int p = 0; p < 4; ++p)
                        pfB[p] = __ldg(Bg + (((ka+3) * 8 + nblk) * 4 + p) * 32 + lane);
                }
            }
        }

        // ---- gelu + GEMM2 partial, h fed straight from registers ----
        const int colbase = nc * 128 + wn * 64;
        #pragma unroll
        for (int na = 0; na < 8; ++na) {
            int c = colbase + na * 8 + 2 * (lane & 3);
            float b1a = b1s[c], b1b = b1s[c + 1];
            u32 A2[2][4];
            #pragma unroll
            for (int m = 0; m < 2; ++m) {
                float h0 = gelu_t(d1[m][na][0] + b1a);
                float h1 = gelu_t(d1[m][na][1] + b1b);
                float h2 = gelu_t(d1[m][na][2] + b1a);
                float h3 = gelu_t(d1[m][na][3] + b1b);
                // A-frag order for permuted k: {(r,k),(r+8,k),(r,k+4),(r+8,k+4)} = {h0,h2,h1,h3}
                A2[m][0] = tf32b(h0); A2[m][1] = tf32b(h2);
                A2[m][2] = tf32b(h1); A2[m][3] = tf32b(h3);
            }
            int gka = nc * 16 + wn * 8 + na;
            #pragma unroll
            for (int pa = 0; pa < 2; ++pa) {
                float4 w = *(const float4*)&W2s[((gka * 2 + pa) * 32 + lane) * 4];
                u32 bx=__float_as_uint(w.x), by=__float_as_uint(w.y);
                u32 bz=__float_as_uint(w.z), bw=__float_as_uint(w.w);
                MMA4(d2[0][2*pa],   A2[0], bx, by);
                MMA4(d2[1][2*pa],   A2[1], bx, by);
                MMA4(d2[0][2*pa+1], A2[0], bz, bw);
                MMA4(d2[1][2*pa+1], A2[1], bz, bw);
            }
        }
    }

    __syncthreads();   // all Zf reads done before red overwrites it

    // ---- cross-wn reduction: wn=1 stores its partial d2, wn=0 adds ----
    if (wn == 1) {
        float* rp = red + (wm * 32 + lane) * 36;
        #pragma unroll
        for (int m = 0; m < 2; ++m)
            #pragma unroll
            for (int a = 0; a < 4; ++a)
                *(float4*)&rp[(m * 4 + a) * 4] =
                    make_float4(d2[m][a][0], d2[m][a][1], d2[m][a][2], d2[m][a][3]);
    }
    __syncthreads();

    if (wn == 0) {
        const float* rp = red + (wm * 32 + lane) * 36;
        #pragma unroll
        for (int m = 0; m < 2; ++m)
            #pragma unroll
            for (int a = 0; a < 4; ++a) {
                float4 v = *(const float4*)&rp[(m * 4 + a) * 4];
                d2[m][a][0] += v.x; d2[m][a][1] += v.y;
                d2[m][a][2] += v.z; d2[m][a][3] += v.w;
            }
        // epilogue: dst[row][c..c+1] = x + 0.1*(d2 + b2)
        #pragma unroll
        for (int m = 0; m < 2; ++m)
            #pragma unroll
            for (int rr = 0; rr < 2; ++rr) {
                int row = wm * 32 + m * 16 + rr * 8 + (lane >> 2);
                if (row < rows_valid) {
                    size_t rb = (size_t)(m0 + row) * Dn;
                    #pragma unroll
                    for (int a = 0; a < 4; ++a) {
                        int c = a * 8 + 2 * (lane & 3);
                        float2 xv = __ldg((const float2*)(src + rb + c));
                        float2 ov;
                        ov.x = xv.x + 0.1f * (d2[m][a][rr*2]     + b2s[c]);
                        ov.y = xv.y + 0.1f * (d2[m][a][rr*2 + 1] + b2s[c+1]);
                        *(float2*)(dst + rb + c) = ov;
                    }
                }
            }
    } else {
        // static dims 32..39 (unchanged by Euler step)
        int row = (wid - 4) * 32 + lane;
        if (row < rows_valid) {
            size_t rb = (size_t)(m0 + row) * Dn;
            float4 s0 = __ldg((const float4*)(src + rb + 32));
            float4 s1 = __ldg((const float4*)(src + rb + 36));
            *(float4*)(dst + rb + 32) = s0;
            *(float4*)(dst + rb + 36) = s1;
        }
    }
}

extern "C" void kernel_launch(void* const* d_in, const int* in_sizes, int n_in,
                              void* d_out, int out_size)
{
    const float* x     = (const float*)d_in[0];
    const int*   index = (const int*)  d_in[1];
    const float* W1    = (const float*)d_in[2];
    const float* b1    = (const float*)d_in[3];
    const float* W2    = (const float*)d_in[4];
    const float* b2    = (const float*)d_in[5];
    float* out = (float*)d_out;

    float *buf = nullptr, *w1f = nullptr, *w2f = nullptr;
    cudaGetSymbolAddress((void**)&buf, g_xbuf);
    cudaGetSymbolAddress((void**)&w1f, g_W1f);
    cudaGetSymbolAddress((void**)&w2f, g_W2f);

    cudaFuncSetAttribute(step_kernel, cudaFuncAttributeMaxDynamicSharedMemorySize, SMEM_BYTES);

    prep_w1f<<<(KA1*8*4*32*4 + 255)/256, 256>>>(W1);
    prep_w2f<<<(64*2*32*4 + 255)/256, 256>>>(W2);

    dim3 grid(NBLK), block(NTH);
    step_kernel<<<grid, block, SMEM_BYTES>>>(x,   buf, index, w1f, w2f, b1, b2);
    step_kernel<<<grid, block, SMEM_BYTES>>>(buf, out, index, w1f, w2f, b1, b2);
    step_kernel<<<grid, block, SMEM_BYTES>>>(out, buf, index, w1f, w2f, b1, b2);
    step_kernel<<<grid, block, SMEM_BYTES>>>(buf, out, index, w1f, w2f, b1, b2);
}

// round 4
// speedup vs baseline: 4.0049x; 1.2213x over previous
#include <cuda_runtime.h>
#include <cstdint>

typedef unsigned int u32;

// ---------------- problem constants ----------------
#define Bn 8
#define Nn 40962
#define Dn 40
#define Hn 512
#define DDn 32
#define KTOT 160               // 4 neighbors * 40
#define M_TOT (Bn*Nn)          // 327696
#define TMm 128                // rows per CTA
#define NTH 512
#define NBLK ((M_TOT + TMm - 1)/TMm)   // 2561
#define KA1 20                 // GEMM1 k-atoms (160/8)

// smem (floats): Zfrag 20480 | b1 512 | b2 32 | bas 512
#define SM_Z    0
#define SM_B1   20480
#define SM_B2   (SM_B1 + 512)
#define SM_BAS  (SM_B2 + 32)
#define SM_FLOATS (SM_BAS + 512)
#define SMEM_BYTES (SM_FLOATS*4)       // 86144

// ---------------- helpers ----------------
__device__ __forceinline__ u32 tf32b(float x) {
    u32 r; asm("cvt.rna.tf32.f32 %0, %1;" : "=r"(r) : "f"(x));
    return r;
}
__device__ __forceinline__ float gelu_t(float x) {
    float u = x * (0.7978845608028654f + 0.0356774081f * x * x);
    float t; asm("tanh.approx.f32 %0, %1;" : "=f"(t) : "f"(u));
    return 0.5f * x * (1.0f + t);
}

// m16n8k8 tf32 HMMA: D(f32) += A(tf32) * B(tf32)
#define MMA4(D, A, b0, b1) \
    asm("mma.sync.aligned.m16n8k8.row.col.f32.tf32.tf32.f32 " \
        "{%0,%1,%2,%3}, {%4,%5,%6,%7}, {%8,%9}, {%0,%1,%2,%3};" \
        : "+f"((D)[0]), "+f"((D)[1]), "+f"((D)[2]), "+f"((D)[3]) \
        : "r"((A)[0]), "r"((A)[1]), "r"((A)[2]), "r"((A)[3]), "r"(b0), "r"(b1))

// ---------------- global scratch ----------------
// W1 B-fragments: [ka(20)][nblk(8)][pair(4)][lane(32)][q(4)]
__device__ float g_W1f[KA1 * 8 * 4 * 32 * 4];        // 163840 floats
// W2 B-fragments (k-permuted to match GEMM1 D layout): [gka(64)][pair(2)][lane(32)][q(4)]
__device__ float g_W2f[64 * 2 * 32 * 4];             // 16384 floats
__device__ float g_xbuf[(size_t)M_TOT * Dn];         // ping-pong state

// prep: W1 -> B-fragment order, tf32-rounded.
// value(ka,nblk,pair,lane,q): k = ka*8 + lane%4 + (q%2)*4
//                             n = nblk*64 + pair*16 + (q/2)*8 + lane/4
__global__ void prep_w1f(const float* __restrict__ W1) {
    int i = blockIdx.x * 256 + threadIdx.x;
    if (i >= KA1 * 8 * 4 * 32 * 4) return;
    int q    = i & 3;
    int lane = (i >> 2) & 31;
    int pair = (i >> 7) & 3;
    int nblk = (i >> 9) & 7;
    int ka   = i >> 12;
    int k = ka * 8 + (lane & 3) + (q & 1) * 4;
    int n = nblk * 64 + pair * 16 + (q >> 1) * 8 + (lane >> 2);
    g_W1f[i] = __uint_as_float(tf32b(__ldg(&W1[k * Hn + n])));
}

// prep: W2 -> B-fragment order with k-permutation pi(k) = (k<4) ? 2k : 2(k-4)+1.
// value(gka,pair,lane,q): w2row = gka*8 + 2*(lane%4) + (q%2)
//                         n     = pair*16 + (q/2)*8 + lane/4
__global__ void prep_w2f(const float* __restrict__ W2) {
    int i = blockIdx.x * 256 + threadIdx.x;
    if (i >= 64 * 2 * 32 * 4) return;
    int q    = i & 3;
    int lane = (i >> 2) & 31;
    int pair = (i >> 7) & 1;
    int gka  = i >> 8;
    int r = gka * 8 + 2 * (lane & 3) + (q & 1);
    int n = pair * 16 + (q >> 1) * 8 + (lane >> 4 == 0 ? (lane >> 2) : (lane >> 2));
    n = pair * 16 + (q >> 1) * 8 + (lane >> 2);
    g_W2f[i] = __uint_as_float(tf32b(__ldg(&W2[r * DDn + n])));
}

// ---------------- fused Euler step ----------------
__global__ void __launch_bounds__(NTH, 1)
step_kernel(const float* __restrict__ src, float* __restrict__ dst,
            const int* __restrict__ index,
            const float* __restrict__ W1f, const float* __restrict__ W2f,
            const float* __restrict__ b1, const float* __restrict__ b2)
{
    extern __shared__ float sm[];
    float* Zf  = sm + SM_Z;      // A-frags of Z: [mb(8)][ka(20)][lane(32)][slot(4)]
    float* b1s = sm + SM_B1;
    float* b2s = sm + SM_B2;
    int*   bas = (int*)(sm + SM_BAS);
    float* red = sm + SM_Z;      // reduction scratch reuses Zf after GEMMs

    const int tid  = threadIdx.x;
    const int lane = tid & 31;
    const int wid  = tid >> 5;
    const int wm   = wid & 3;    // M warp: rows wm*32
    const int wn   = wid >> 2;   // N warp: 32-col slice within each 128-chunk (0..3)
    const int m0   = blockIdx.x * TMm;
    const int rows_valid = min(TMm, M_TOT - m0);

    // gather bases (one per thread)
    {
        int r = tid >> 2, k = tid & 3;
        int base = 0;
        if (r < rows_valid) {
            int m = m0 + r, b = m / Nn, n = m - b * Nn;
            base = (b * Nn + __ldg(&index[n * 4 + k])) * Dn;
        }
        bas[tid] = base;
    }
    // biases
    if (tid < 128) ((float4*)b1s)[tid] = __ldg(((const float4*)b1) + tid);
    if (tid < 8)   ((float4*)b2s)[tid] = __ldg(((const float4*)b2) + tid);
    __syncthreads();

    // ---- gather Z -> A-fragment layout, tf32-rounded ----
    // element (row r, K): mb=r/16, rr=r%16, ka=K/8, c=K%8
    //   lane' = (rr%8)*4 + c%4 ; slot = rr/8 + 2*(c/4)
    #pragma unroll 1
    for (int it = 0; it < 10; ++it) {
        int t  = it * NTH + tid;            // 5120 float4
        int d4 = t % 10, rk = t / 10;
        int r  = rk >> 2, kn = rk & 3;
        float4 v = __ldg((const float4*)(src + bas[rk] + d4 * 4));
        int K  = kn * 40 + d4 * 4;
        int ka = K >> 3, c0 = K & 7;
        int mb = r >> 4, rr = r & 15;
        int slot = (rr >> 3) + ((c0 >> 2) << 1);
        int idx0 = (((mb * KA1 + ka) * 32) + (rr & 7) * 4) * 4 + slot;
        Zf[idx0]      = __uint_as_float(tf32b(v.x));
        Zf[idx0 + 4]  = __uint_as_float(tf32b(v.y));
        Zf[idx0 + 8]  = __uint_as_float(tf32b(v.z));
        Zf[idx0 + 12] = __uint_as_float(tf32b(v.w));
    }
    __syncthreads();

    float d2[2][4][4];
    #pragma unroll
    for (int m = 0; m < 2; ++m)
        #pragma unroll
        for (int a = 0; a < 4; ++a)
            #pragma unroll
            for (int q = 0; q < 4; ++q) d2[m][a][q] = 0.f;

    const float4* Bg  = (const float4*)W1f;
    const float4* B2g = (const float4*)W2f;
    const int nblk_sub = wn >> 1;      // which 64-col block half within the 128-chunk
    const int p0       = (wn & 1) * 2; // pair base within that 64-col block

    // ---- 4 H-chunks of 128 cols; each warp owns a 32-row x 32-col tile ----
    #pragma unroll 1
    for (int nc = 0; nc < 4; ++nc) {
        const int nblk = nc * 2 + nblk_sub;
        float d1[2][4][4];
        #pragma unroll
        for (int m = 0; m < 2; ++m)
            #pragma unroll
            for (int a = 0; a < 4; ++a)
                #pragma unroll
                for (int q = 0; q < 4; ++q) d1[m][a][q] = 0.f;

        // distance-2 register prefetch of W1 B-frags (L2-resident)
        float4 pfA[2], pfB[2];
        #pragma unroll
        for (int p = 0; p < 2; ++p) {
            pfA[p] = __ldg(Bg + ((0 * 8 + nblk) * 4 + p0 + p) * 32 + lane);
            pfB[p] = __ldg(Bg + ((1 * 8 + nblk) * 4 + p0 + p) * 32 + lane);
        }

        #pragma unroll 1
        for (int ka = 0; ka < KA1; ka += 2) {
            // ---- even k-atom (pfA) ----
            {
                u32 a0[4], a1[4];
                float4 av0 = *(const float4*)&Zf[(((wm*2+0) * KA1 + ka) * 32 + lane) * 4];
                float4 av1 = *(const float4*)&Zf[(((wm*2+1) * KA1 + ka) * 32 + lane) * 4];
                a0[0]=__float_as_uint(av0.x); a0[1]=__float_as_uint(av0.y);
                a0[2]=__float_as_uint(av0.z); a0[3]=__float_as_uint(av0.w);
                a1[0]=__float_as_uint(av1.x); a1[1]=__float_as_uint(av1.y);
                a1[2]=__float_as_uint(av1.z); a1[3]=__float_as_uint(av1.w);
                #pragma unroll
                for (int p = 0; p < 2; ++p) {
                    u32 bx=__float_as_uint(pfA[p].x), by=__float_as_uint(pfA[p].y);
                    u32 bz=__float_as_uint(pfA[p].z), bw=__float_as_uint(pfA[p].w);
                    MMA4(d1[0][2*p],   a0, bx, by);
                    MMA4(d1[1][2*p],   a1, bx, by);
                    MMA4(d1[0][2*p+1], a0, bz, bw);
                    MMA4(d1[1][2*p+1], a1, bz, bw);
                }
                if (ka + 2 < KA1) {
                    #pragma unroll
                    for (int p = 0; p < 2; ++p)
                        pfA[p] = __ldg(Bg + (((ka+2) * 8 + nblk) * 4 + p0 + p) * 32 + lane);
                }
            }
            // ---- odd k-atom (pfB) ----
            {
                u32 a0[4], a1[4];
                float4 av0 = *(const float4*)&Zf[(((wm*2+0) * KA1 + ka+1) * 32 + lane) * 4];
                float4 av1 = *(const float4*)&Zf[(((wm*2+1) * KA1 + ka+1) * 32 + lane) * 4];
                a0[0]=__float_as_uint(av0.x); a0[1]=__float_as_uint(av0.y);
                a0[2]=__float_as_uint(av0.z); a0[3]=__float_as_uint(av0.w);
                a1[0]=__float_as_uint(av1.x); a1[1]=__float_as_uint(av1.y);
                a1[2]=__float_as_uint(av1.z); a1[3]=__float_as_uint(av1.w);
                #pragma unroll
                for (int p = 0; p < 2; ++p) {
                    u32 bx=__float_as_uint(pfB[p].x), by=__float_as_uint(pfB[p].y);
                    u32 bz=__float_as_uint(pfB[p].z), bw=__float_as_uint(pfB[p].w);
                    MMA4(d1[0][2*p],   a0, bx, by);
                    MMA4(d1[1][2*p],   a1, bx, by);
                    MMA4(d1[0][2*p+1], a0, bz, bw);
                    MMA4(d1[1][2*p+1], a1, bz, bw);
                }
                if (ka + 3 < KA1) {
                    #pragma unroll
                    for (int p = 0; p < 2; ++p)
                        pfB[p] = __ldg(Bg + (((ka+3) * 8 + nblk) * 4 + p0 + p) * 32 + lane);
                }
            }
        }

        // ---- gelu + GEMM2 partial, h fed straight from registers ----
        const int colbase = nc * 128 + wn * 32;
        #pragma unroll
        for (int na = 0; na < 4; ++na) {
            int c = colbase + na * 8 + 2 * (lane & 3);
            float b1a = b1s[c], b1b = b1s[c + 1];
            u32 A2[2][4];
            #pragma unroll
            for (int m = 0; m < 2; ++m) {
                float h0 = gelu_t(d1[m][na][0] + b1a);
                float h1 = gelu_t(d1[m][na][1] + b1b);
                float h2 = gelu_t(d1[m][na][2] + b1a);
                float h3 = gelu_t(d1[m][na][3] + b1b);
                // A-frag order for permuted k: {(r,k),(r+8,k),(r,k+4),(r+8,k+4)} = {h0,h2,h1,h3}
                A2[m][0] = tf32b(h0); A2[m][1] = tf32b(h2);
                A2[m][2] = tf32b(h1); A2[m][3] = tf32b(h3);
            }
            int gka = nc * 16 + wn * 4 + na;
            #pragma unroll
            for (int pa = 0; pa < 2; ++pa) {
                float4 w = __ldg(B2g + (gka * 2 + pa) * 32 + lane);
                u32 bx=__float_as_uint(w.x), by=__float_as_uint(w.y);
                u32 bz=__float_as_uint(w.z), bw=__float_as_uint(w.w);
                MMA4(d2[0][2*pa],   A2[0], bx, by);
                MMA4(d2[1][2*pa],   A2[1], bx, by);
                MMA4(d2[0][2*pa+1], A2[0], bz, bw);
                MMA4(d2[1][2*pa+1], A2[1], bz, bw);
            }
        }
    }

    __syncthreads();   // all Zf reads done before red overwrites it

    // ---- cross-wn reduction: wn=1..3 store partial d2, wn=0 adds ----
    if (wn >= 1) {
        float* rp = red + ((wn - 1) * 128 + wm * 32 + lane) * 36;
        #pragma unroll
        for (int m = 0; m < 2; ++m)
            #pragma unroll
            for (int a = 0; a < 4; ++a)
                *(float4*)&rp[(m * 4 + a) * 4] =
                    make_float4(d2[m][a][0], d2[m][a][1], d2[m][a][2], d2[m][a][3]);
    }
    __syncthreads();

    if (wn == 0) {
        #pragma unroll
        for (int s = 0; s < 3; ++s) {
            const float* rp = red + (s * 128 + wm * 32 + lane) * 36;
            #pragma unroll
            for (int m = 0; m < 2; ++m)
                #pragma unroll
                for (int a = 0; a < 4; ++a) {
                    float4 v = *(const float4*)&rp[(m * 4 + a) * 4];
                    d2[m][a][0] += v.x; d2[m][a][1] += v.y;
                    d2[m][a][2] += v.z; d2[m][a][3] += v.w;
                }
        }
        // epilogue: dst[row][c..c+1] = x + 0.1*(d2 + b2)
        #pragma unroll
        for (int m = 0; m < 2; ++m)
            #pragma unroll
            for (int rr = 0; rr < 2; ++rr) {
                int row = wm * 32 + m * 16 + rr * 8 + (lane >> 2);
                if (row < rows_valid) {
                    size_t rb = (size_t)(m0 + row) * Dn;
                    #pragma unroll
                    for (int a = 0; a < 4; ++a) {
                        int c = a * 8 + 2 * (lane & 3);
                        float2 xv = __ldg((const float2*)(src + rb + c));
                        float2 ov;
                        ov.x = xv.x + 0.1f * (d2[m][a][rr*2]     + b2s[c]);
                        ov.y = xv.y + 0.1f * (d2[m][a][rr*2 + 1] + b2s[c+1]);
                        *(float2*)(dst + rb + c) = ov;
                    }
                }
            }
    } else if (wn == 1) {
        // static dims 32..39 (unchanged by Euler step)
        int row = wm * 32 + lane;
        if (row < rows_valid) {
            size_t rb = (size_t)(m0 + row) * Dn;
            float4 s0 = __ldg((const float4*)(src + rb + 32));
            float4 s1 = __ldg((const float4*)(src + rb + 36));
            *(float4*)(dst + rb + 32) = s0;
            *(float4*)(dst + rb + 36) = s1;
        }
    }
}

extern "C" void kernel_launch(void* const* d_in, const int* in_sizes, int n_in,
                              void* d_out, int out_size)
{
    const float* x     = (const float*)d_in[0];
    const int*   index = (const int*)  d_in[1];
    const float* W1    = (const float*)d_in[2];
    const float* b1    = (const float*)d_in[3];
    const float* W2    = (const float*)d_in[4];
    const float* b2    = (const float*)d_in[5];
    float* out = (float*)d_out;

    float *buf = nullptr, *w1f = nullptr, *w2f = nullptr;
    cudaGetSymbolAddress((void**)&buf, g_xbuf);
    cudaGetSymbolAddress((void**)&w1f, g_W1f);
    cudaGetSymbolAddress((void**)&w2f, g_W2f);

    cudaFuncSetAttribute(step_kernel, cudaFuncAttributeMaxDynamicSharedMemorySize, SMEM_BYTES);

    prep_w1f<<<(KA1*8*4*32*4 + 255)/256, 256>>>(W1);
    prep_w2f<<<(64*2*32*4 + 255)/256, 256>>>(W2);

    dim3 grid(NBLK), block(NTH);
    step_kernel<<<grid, block, SMEM_BYTES>>>(x,   buf, index, w1f, w2f, b1, b2);
    step_kernel<<<grid, block, SMEM_BYTES>>>(buf, out, index, w1f, w2f, b1, b2);
    step_kernel<<<grid, block, SMEM_BYTES>>>(out, buf, index, w1f, w2f, b1, b2);
    step_kernel<<<grid, block, SMEM_BYTES>>>(buf, out, index, w1f, w2f, b1, b2);
}

// round 5
// speedup vs baseline: 6.1764x; 1.5422x over previous
#include <cuda_runtime.h>
#include <cuda_fp16.h>
#include <cstdint>

typedef unsigned int u32;

// ---------------- problem constants ----------------
#define Bn 8
#define Nn 40962
#define Dn 40
#define Hn 512
#define DDn 32
#define KTOT 160               // 4 neighbors * 40
#define M_TOT (Bn*Nn)          // 327696
#define TMm 128                // rows per CTA
#define NTH 512
#define NBLK ((M_TOT + TMm - 1)/TMm)   // 2561
#define KA16 10                // GEMM1 k-atoms of 16 (160/16)

// smem (float indices): region A = max(Zf 10240 u32, red 13824 f32) = 13824 floats
#define SM_Z    0
#define SM_B1   13824
#define SM_B2   (SM_B1 + 512)
#define SM_BAS  (SM_B2 + 32)
#define SM_FLOATS (SM_BAS + 512)
#define SMEM_BYTES (SM_FLOATS*4)       // 59520

// ---------------- helpers ----------------
__device__ __forceinline__ float gelu_t(float x) {
    float u = x * (0.7978845608028654f + 0.0356774081f * x * x);
    float t; asm("tanh.approx.f32 %0, %1;" : "=f"(t) : "f"(u));
    return 0.5f * x * (1.0f + t);
}
__device__ __forceinline__ u32 pack2(float a, float b) {
    __half2 h = __floats2half2_rn(a, b);
    return *(u32*)&h;
}

// m16n8k16 fp16 HMMA: D(f32) += A(f16) * B(f16)
#define MMAH(D, A, b0, b1) \
    asm("mma.sync.aligned.m16n8k16.row.col.f32.f16.f16.f32 " \
        "{%0,%1,%2,%3}, {%4,%5,%6,%7}, {%8,%9}, {%0,%1,%2,%3};" \
        : "+f"((D)[0]), "+f"((D)[1]), "+f"((D)[2]), "+f"((D)[3]) \
        : "r"((A)[0]), "r"((A)[1]), "r"((A)[2]), "r"((A)[3]), "r"(b0), "r"(b1))

// ---------------- global scratch ----------------
// W1 fp16 B-fragments: [ka16(10)][npair(32)][lane(32)] x uint4 (2 n-atoms per load)
__device__ uint4 g_W1h[KA16 * 32 * 32];              // 163840 B
// W2 fp16 B-fragments, natural k order: [gka16(32)][pa(2)][lane(32)] x uint4
__device__ uint4 g_W2h[32 * 2 * 32];                 // 32768 B
__device__ float g_xbuf[(size_t)M_TOT * Dn];         // ping-pong state

// prep: W1 -> fp16 B-frag order.
// u32 i -> (ka, npair, lane, q): k = ka*16 + (lane%4)*2 + {0,1} + (q&1)*8
//                                n = npair*16 + (q>>1)*8 + lane/4
__global__ void prep_w1h(const float* __restrict__ W1) {
    int i = blockIdx.x * 256 + threadIdx.x;
    if (i >= KA16 * 32 * 32 * 4) return;
    int q    = i & 3;
    int lane = (i >> 2) & 31;
    int np   = (i >> 7) & 31;
    int ka   = i >> 12;
    int k = ka * 16 + (lane & 3) * 2 + (q & 1) * 8;
    int n = np * 16 + ((q >> 1) << 3) + (lane >> 2);
    float v0 = __ldg(&W1[(size_t)k * Hn + n]);
    float v1 = __ldg(&W1[(size_t)(k + 1) * Hn + n]);
    ((u32*)g_W1h)[i] = pack2(v0, v1);
}

// prep: W2 -> fp16 B-frag order (identity k mapping).
// (gka, pa, lane, q): row = gka*16 + (lane%4)*2 + {0,1} + (q&1)*8
//                     n   = pa*16 + (q>>1)*8 + lane/4
__global__ void prep_w2h(const float* __restrict__ W2) {
    int i = blockIdx.x * 256 + threadIdx.x;
    if (i >= 32 * 2 * 32 * 4) return;
    int q    = i & 3;
    int lane = (i >> 2) & 31;
    int pa   = (i >> 7) & 1;
    int gka  = i >> 8;
    int r = gka * 16 + (lane & 3) * 2 + (q & 1) * 8;
    int n = pa * 16 + ((q >> 1) << 3) + (lane >> 2);
    float v0 = __ldg(&W2[r * DDn + n]);
    float v1 = __ldg(&W2[(r + 1) * DDn + n]);
    ((u32*)g_W2h)[i] = pack2(v0, v1);
}

// ---------------- fused Euler step ----------------
__global__ void __launch_bounds__(NTH, 1)
step_kernel(const float* __restrict__ src, float* __restrict__ dst,
            const int* __restrict__ index,
            const uint4* __restrict__ W1h, const uint4* __restrict__ W2h,
            const float* __restrict__ b1, const float* __restrict__ b2)
{
    extern __shared__ float sm[];
    u32*   Zu  = (u32*)(sm + SM_Z);   // fp16 A-frags: [mb(8)][ka16(10)][lane(32)][slot(4)] u32
    float* b1s = sm + SM_B1;
    float* b2s = sm + SM_B2;
    int*   bas = (int*)(sm + SM_BAS);
    float* red = sm + SM_Z;           // reduction scratch reuses Zf region after GEMMs

    const int tid  = threadIdx.x;
    const int lane = tid & 31;
    const int wid  = tid >> 5;
    const int wm   = wid & 3;    // M warp: rows wm*32
    const int wn   = wid >> 2;   // N warp: 32-col slice within each 128-chunk (0..3)
    const int m0   = blockIdx.x * TMm;
    const int rows_valid = min(TMm, M_TOT - m0);

    // gather bases (one per thread: 128 rows x 4 neighbors)
    {
        int r = tid >> 2, k = tid & 3;
        int base = 0;
        if (r < rows_valid) {
            int m = m0 + r, b = m / Nn, n = m - b * Nn;
            base = (b * Nn + __ldg(&index[n * 4 + k])) * Dn;
        }
        bas[tid] = base;
    }
    if (tid < 128) ((float4*)b1s)[tid] = __ldg(((const float4*)b1) + tid);
    if (tid < 8)   ((float4*)b2s)[tid] = __ldg(((const float4*)b2) + tid);
    __syncthreads();

    // ---- gather Z -> fp16 A-fragment layout ----
    // element (row r, K): mb=r/16, rr=r%16, ka=K/16, kk=K%16
    //   lane' = (rr%8)*4 + (kk%8)/2 ; slot = rr/8 + 2*(kk/8) ; half = kk%2
    #pragma unroll 1
    for (int it = 0; it < 10; ++it) {
        int t  = it * NTH + tid;            // 5120 float4
        int d4 = t % 10, rk = t / 10;
        int r  = rk >> 2, kn = rk & 3;
        float4 v = __ldg((const float4*)(src + bas[rk] + d4 * 4));
        int K  = kn * 40 + d4 * 4;
        int ka = K >> 4, kk = K & 15;
        int mb = r >> 4, rr = r & 15;
        int lane0 = ((rr & 7) << 2) + ((kk & 7) >> 1);
        int slot  = (rr >> 3) + ((kk >> 3) << 1);
        int base  = ((mb * KA16 + ka) * 32 + lane0) * 4 + slot;
        Zu[base]     = pack2(v.x, v.y);
        Zu[base + 4] = pack2(v.z, v.w);
    }
    __syncthreads();

    float d2[2][4][4];
    #pragma unroll
    for (int m = 0; m < 2; ++m)
        #pragma unroll
        for (int a = 0; a < 4; ++a)
            #pragma unroll
            for (int q = 0; q < 4; ++q) d2[m][a][q] = 0.f;

    const uint4* Za = (const uint4*)Zu;
    const int np0 = wn * 2;      // warp's first npair within each 128-col chunk

    // ---- 4 H-chunks of 128 cols; each warp owns a 32-row x 32-col tile ----
    #pragma unroll 1
    for (int nc = 0; nc < 4; ++nc) {
        const int npA = nc * 8 + np0;     // warp's npair indices: npA, npA+1
        float d1[2][4][4];
        #pragma unroll
        for (int m = 0; m < 2; ++m)
            #pragma unroll
            for (int a = 0; a < 4; ++a)
                #pragma unroll
                for (int q = 0; q < 4; ++q) d1[m][a][q] = 0.f;

        // distance-2 register prefetch of W1 fp16 B-frags (L2-resident)
        uint4 pfA[2], pfB[2];
        #pragma unroll
        for (int p = 0; p < 2; ++p) {
            pfA[p] = __ldg(W1h + (0 * 32 + npA + p) * 32 + lane);
            pfB[p] = __ldg(W1h + (1 * 32 + npA + p) * 32 + lane);
        }

        #pragma unroll 1
        for (int ka = 0; ka < KA16; ka += 2) {
            // ---- even k-atom (pfA) ----
            {
                uint4 av0 = Za[((wm * 2 + 0) * KA16 + ka) * 32 + lane];
                uint4 av1 = Za[((wm * 2 + 1) * KA16 + ka) * 32 + lane];
                u32 a0[4] = {av0.x, av0.y, av0.z, av0.w};
                u32 a1[4] = {av1.x, av1.y, av1.z, av1.w};
                #pragma unroll
                for (int p = 0; p < 2; ++p) {
                    MMAH(d1[0][2*p],   a0, pfA[p].x, pfA[p].y);
                    MMAH(d1[1][2*p],   a1, pfA[p].x, pfA[p].y);
                    MMAH(d1[0][2*p+1], a0, pfA[p].z, pfA[p].w);
                    MMAH(d1[1][2*p+1], a1, pfA[p].z, pfA[p].w);
                }
                if (ka + 2 < KA16) {
                    #pragma unroll
                    for (int p = 0; p < 2; ++p)
                        pfA[p] = __ldg(W1h + ((ka + 2) * 32 + npA + p) * 32 + lane);
                }
            }
            // ---- odd k-atom (pfB) ----
            {
                uint4 av0 = Za[((wm * 2 + 0) * KA16 + ka + 1) * 32 + lane];
                uint4 av1 = Za[((wm * 2 + 1) * KA16 + ka + 1) * 32 + lane];
                u32 a0[4] = {av0.x, av0.y, av0.z, av0.w};
                u32 a1[4] = {av1.x, av1.y, av1.z, av1.w};
                #pragma unroll
                for (int p = 0; p < 2; ++p) {
                    MMAH(d1[0][2*p],   a0, pfB[p].x, pfB[p].y);
                    MMAH(d1[1][2*p],   a1, pfB[p].x, pfB[p].y);
                    MMAH(d1[0][2*p+1], a0, pfB[p].z, pfB[p].w);
                    MMAH(d1[1][2*p+1], a1, pfB[p].z, pfB[p].w);
                }
                if (ka + 3 < KA16) {
                    #pragma unroll
                    for (int p = 0; p < 2; ++p)
                        pfB[p] = __ldg(W1h + ((ka + 3) * 32 + npA + p) * 32 + lane);
                }
            }
        }

        // ---- gelu + GEMM2 partial: h packed to fp16 straight from registers ----
        // k-enum per gka16: k0-7 = even n-atom cols (pattern 2c,2c+1), k8-15 = odd atom.
        const int colbase = nc * 128 + wn * 32;
        const int ccol    = 2 * (lane & 3);
        #pragma unroll
        for (int pg = 0; pg < 2; ++pg) {
            int cE = colbase + (2 * pg) * 8 + ccol;       // even atom cols
            int cO = cE + 8;                              // odd atom cols
            float bEa = b1s[cE], bEb = b1s[cE + 1];
            float bOa = b1s[cO], bOb = b1s[cO + 1];
            u32 A2[2][4];
            #pragma unroll
            for (int m = 0; m < 2; ++m) {
                A2[m][0] = pack2(gelu_t(d1[m][2*pg][0]   + bEa), gelu_t(d1[m][2*pg][1]   + bEb));
                A2[m][1] = pack2(gelu_t(d1[m][2*pg][2]   + bEa), gelu_t(d1[m][2*pg][3]   + bEb));
                A2[m][2] = pack2(gelu_t(d1[m][2*pg+1][0] + bOa), gelu_t(d1[m][2*pg+1][1] + bOb));
                A2[m][3] = pack2(gelu_t(d1[m][2*pg+1][2] + bOa), gelu_t(d1[m][2*pg+1][3] + bOb));
            }
            int gka = nc * 8 + wn * 2 + pg;               // H 16-row block index (0..31)
            #pragma unroll
            for (int pa = 0; pa < 2; ++pa) {
                uint4 w = __ldg(W2h + (gka * 2 + pa) * 32 + lane);
                MMAH(d2[0][2*pa],   A2[0], w.x, w.y);
                MMAH(d2[1][2*pa],   A2[1], w.x, w.y);
                MMAH(d2[0][2*pa+1], A2[0], w.z, w.w);
                MMAH(d2[1][2*pa+1], A2[1], w.z, w.w);
            }
        }
    }

    __syncthreads();   // all Zf reads done before red overwrites it

    // ---- cross-wn reduction: wn=1..3 store partial d2, wn=0 adds ----
    if (wn >= 1) {
        float* rp = red + ((wn - 1) * 128 + wm * 32 + lane) * 36;
        #pragma unroll
        for (int m = 0; m < 2; ++m)
            #pragma unroll
            for (int a = 0; a < 4; ++a)
                *(float4*)&rp[(m * 4 + a) * 4] =
                    make_float4(d2[m][a][0], d2[m][a][1], d2[m][a][2], d2[m][a][3]);
    }
    __syncthreads();

    if (wn == 0) {
        #pragma unroll
        for (int s = 0; s < 3; ++s) {
            const float* rp = red + (s * 128 + wm * 32 + lane) * 36;
            #pragma unroll
            for (int m = 0; m < 2; ++m)
                #pragma unroll
                for (int a = 0; a < 4; ++a) {
                    float4 v = *(const float4*)&rp[(m * 4 + a) * 4];
                    d2[m][a][0] += v.x; d2[m][a][1] += v.y;
                    d2[m][a][2] += v.z; d2[m][a][3] += v.w;
                }
        }
        // epilogue: dst[row][c..c+1] = x + 0.1*(d2 + b2)
        #pragma unroll
        for (int m = 0; m < 2; ++m)
            #pragma unroll
            for (int rr = 0; rr < 2; ++rr) {
                int row = wm * 32 + m * 16 + rr * 8 + (lane >> 2);
                if (row < rows_valid) {
                    size_t rb = (size_t)(m0 + row) * Dn;
                    #pragma unroll
                    for (int a = 0; a < 4; ++a) {
                        int c = a * 8 + 2 * (lane & 3);
                        float2 xv = __ldg((const float2*)(src + rb + c));
                        float2 ov;
                        ov.x = xv.x + 0.1f * (d2[m][a][rr*2]     + b2s[c]);
                        ov.y = xv.y + 0.1f * (d2[m][a][rr*2 + 1] + b2s[c+1]);
                        *(float2*)(dst + rb + c) = ov;
                    }
                }
            }
    } else if (wn == 1) {
        // static dims 32..39 (unchanged by Euler step)
        int row = wm * 32 + lane;
        if (row < rows_valid) {
            size_t rb = (size_t)(m0 + row) * Dn;
            float4 s0 = __ldg((const float4*)(src + rb + 32));
            float4 s1 = __ldg((const float4*)(src + rb + 36));
            *(float4*)(dst + rb + 32) = s0;
            *(float4*)(dst + rb + 36) = s1;
        }
    }
}

extern "C" void kernel_launch(void* const* d_in, const int* in_sizes, int n_in,
                              void* d_out, int out_size)
{
    const float* x     = (const float*)d_in[0];
    const int*   index = (const int*)  d_in[1];
    const float* W1    = (const float*)d_in[2];
    const float* b1    = (const float*)d_in[3];
    const float* W2    = (const float*)d_in[4];
    const float* b2    = (const float*)d_in[5];
    float* out = (float*)d_out;

    float* buf = nullptr;
    uint4 *w1h = nullptr, *w2h = nullptr;
    cudaGetSymbolAddress((void**)&buf, g_xbuf);
    cudaGetSymbolAddress((void**)&w1h, g_W1h);
    cudaGetSymbolAddress((void**)&w2h, g_W2h);

    cudaFuncSetAttribute(step_kernel, cudaFuncAttributeMaxDynamicSharedMemorySize, SMEM_BYTES);

    prep_w1h<<<(KA16*32*32*4 + 255)/256, 256>>>(W1);
    prep_w2h<<<(32*2*32*4 + 255)/256, 256>>>(W2);

    dim3 grid(NBLK), block(NTH);
    step_kernel<<<grid, block, SMEM_BYTES>>>(x,   buf, index, w1h, w2h, b1, b2);
    step_kernel<<<grid, block, SMEM_BYTES>>>(buf, out, index, w1h, w2h, b1, b2);
    step_kernel<<<grid, block, SMEM_BYTES>>>(out, buf, index, w1h, w2h, b1, b2);
    step_kernel<<<grid, block, SMEM_BYTES>>>(buf, out, index, w1h, w2h, b1, b2);
}